// round 7
// baseline (speedup 1.0000x reference)
#include <cuda_runtime.h>

#define EDIM    4096
#define BATCH   8
#define HEADS   32
#define DHEAD   128
#define TPREV   2047
#define TTOT    2048
#define NSPLIT  8
#define TOK_PER_BLOCK 256   // 8 warps * 32 tokens

// ---------------- scratch (device globals, no allocation) ----------------
__device__ float g_q[BATCH * EDIM];
__device__ float g_k[BATCH * EDIM];
__device__ float g_v[BATCH * EDIM];
__device__ float g_attn[BATCH * EDIM];
__device__ float g_pm[BATCH * HEADS * NSPLIT];
__device__ float g_pl[BATCH * HEADS * NSPLIT];
__device__ float g_pacc[BATCH * HEADS * NSPLIT * DHEAD];

// ---------------- GEMV: 1 row/warp, 8 rows/block, x via L1 ----------------
// Y[b][row] = sum_i X[b][i]*W[row][i] + bias[row]
// Each warp streams ONE distinct 16KB W row from DRAM; the 128KB x matrix
// is L2/L1-resident and re-read per warp (L1 hits). No smem, no syncs,
// low regs -> high occupancy; grid 512 (x3 for qkv) keeps all SMs busy.
__device__ __forceinline__ void gemv_warp_row(const float* __restrict__ X,
                                              const float* __restrict__ W,
                                              const float* __restrict__ bias,
                                              float* __restrict__ Y) {
    const int warp = threadIdx.x >> 5;
    const int lane = threadIdx.x & 31;
    const int row  = blockIdx.x * 8 + warp;

    const float* wrow = W + (size_t)row * EDIM;

    float acc[8];
#pragma unroll
    for (int b = 0; b < 8; ++b) acc[b] = 0.f;

#pragma unroll 4
    for (int k = 0; k < EDIM / 128; ++k) {            // 32 iterations
        const int i = (k * 32 + lane) * 4;
        const float4 w4 = *(const float4*)&wrow[i];
#pragma unroll
        for (int b = 0; b < 8; ++b) {
            const float4 x4 = *(const float4*)&X[b * EDIM + i];
            acc[b] += w4.x * x4.x + w4.y * x4.y + w4.z * x4.z + w4.w * x4.w;
        }
    }

#pragma unroll
    for (int b = 0; b < 8; ++b) {
        float v = acc[b];
#pragma unroll
        for (int s = 16; s > 0; s >>= 1)
            v += __shfl_xor_sync(0xffffffffu, v, s);
        acc[b] = v;
    }
    if (lane < 8)
        Y[lane * EDIM + row] = acc[lane] + bias[row];
}

// QKV fused over blockIdx.y; destinations are device globals referenced
// from DEVICE code only.
__global__ void qkv_gemv(const float* __restrict__ x,
                         const float* __restrict__ Wq, const float* __restrict__ bq,
                         const float* __restrict__ Wk, const float* __restrict__ bk,
                         const float* __restrict__ Wv, const float* __restrict__ bv) {
    const int p = blockIdx.y;
    const float* W    = (p == 0) ? Wq : (p == 1) ? Wk : Wv;
    const float* bias = (p == 0) ? bq : (p == 1) ? bk : bv;
    float* Y          = (p == 0) ? g_q : (p == 1) ? g_k : g_v;
    gemv_warp_row(x, W, bias, Y);
}

// Output projection: reads g_attn inside device code.
__global__ void out_gemv(const float* __restrict__ Wo,
                         const float* __restrict__ bo,
                         float* __restrict__ out) {
    gemv_warp_row(g_attn, Wo, bo, out);
}

// ---------------- fused cache-copy + flash attention ----------------------
// grid: (NSPLIT, HEADS, BATCH), block 256 (8 warps x 32 tokens each)
// NOTE: the reference slices q AFTER transposing to (b, h, s, d), so
// q[:, -1:] selects the LAST HEAD (h=31), broadcast to all heads.
__global__ void attn_kernel(const float* __restrict__ kc,
                            const float* __restrict__ vc,
                            float* __restrict__ kout,
                            float* __restrict__ vout) {
    const int split = blockIdx.x;
    const int h = blockIdx.y;
    const int b = blockIdx.z;
    const int warp = threadIdx.x >> 5;
    const int lane = threadIdx.x & 31;
    const int bh = b * HEADS + h;

    // q from head 31 for ALL heads (reference broadcast semantics)
    const float4 q4 = *(const float4*)&g_q[b * EDIM + (HEADS - 1) * DHEAD + lane * 4];
    const float scale = 0.08838834764831845f;  // 1/sqrt(128)

    float m = -1e30f, l = 0.f;
    float4 acc = make_float4(0.f, 0.f, 0.f, 0.f);

    const int tok0 = split * TOK_PER_BLOCK + warp * 32;

#pragma unroll 4
    for (int j = 0; j < 32; ++j) {
        const int tok = tok0 + j;
        const float* kp;
        const float* vp;
        if (tok < TPREV) {
            const size_t off = ((size_t)bh * TPREV + tok) * DHEAD;
            kp = kc + off;
            vp = vc + off;
        } else {
            kp = g_k + b * EDIM + h * DHEAD;
            vp = g_v + b * EDIM + h * DHEAD;
        }
        const float4 k4 = *(const float4*)&kp[lane * 4];
        const float4 v4 = *(const float4*)&vp[lane * 4];

        // cache copy rides the same read
        const size_t oo = ((size_t)bh * TTOT + tok) * DHEAD + lane * 4;
        *(float4*)&kout[oo] = k4;
        *(float4*)&vout[oo] = v4;

        float s = q4.x * k4.x + q4.y * k4.y + q4.z * k4.z + q4.w * k4.w;
#pragma unroll
        for (int sh = 16; sh > 0; sh >>= 1)
            s += __shfl_xor_sync(0xffffffffu, s, sh);
        s *= scale;

        const float mn = fmaxf(m, s);
        const float sc = __expf(m - mn);
        const float p  = __expf(s - mn);
        l = l * sc + p;
        acc.x = acc.x * sc + p * v4.x;
        acc.y = acc.y * sc + p * v4.y;
        acc.z = acc.z * sc + p * v4.z;
        acc.w = acc.w * sc + p * v4.w;
        m = mn;
    }

    // combine the 8 warps of this block
    __shared__ float sm_m[8], sm_l[8];
    __shared__ __align__(16) float sm_acc[8][DHEAD];
    if (lane == 0) { sm_m[warp] = m; sm_l[warp] = l; }
    *(float4*)&sm_acc[warp][lane * 4] = acc;
    __syncthreads();

    if (threadIdx.x < DHEAD) {
        const int d = threadIdx.x;
        float M = -1e30f;
#pragma unroll
        for (int w = 0; w < 8; ++w) M = fmaxf(M, sm_m[w]);
        float L = 0.f, A = 0.f;
#pragma unroll
        for (int w = 0; w < 8; ++w) {
            const float e = __expf(sm_m[w] - M);
            L += sm_l[w] * e;
            A += sm_acc[w][d] * e;
        }
        const int idx = bh * NSPLIT + split;
        g_pacc[idx * DHEAD + d] = A;
        if (d == 0) { g_pm[idx] = M; g_pl[idx] = L; }
    }
}

// merge NSPLIT partial softmaxes per (b,h)
__global__ void combine_kernel() {
    const int bh = blockIdx.x;   // 0..255
    const int d = threadIdx.x;   // 0..127
    float M = -1e30f;
#pragma unroll
    for (int s = 0; s < NSPLIT; ++s)
        M = fmaxf(M, g_pm[bh * NSPLIT + s]);
    float L = 0.f, A = 0.f;
#pragma unroll
    for (int s = 0; s < NSPLIT; ++s) {
        const float e = __expf(g_pm[bh * NSPLIT + s] - M);
        L += g_pl[bh * NSPLIT + s] * e;
        A += g_pacc[(bh * NSPLIT + s) * DHEAD + d] * e;
    }
    const int b = bh / HEADS;
    const int h = bh % HEADS;
    g_attn[b * EDIM + h * DHEAD + d] = A / L;
}

// ---------------- launch ---------------------------------------------------
extern "C" void kernel_launch(void* const* d_in, const int* in_sizes, int n_in,
                              void* d_out, int out_size) {
    // Defensive input mapping based on element counts.
    const float *x, *kc, *vc, *Wq, *bq, *Wk, *bk, *Wv, *bv, *Wo, *bo;
    if (in_sizes[0] == BATCH * EDIM) {
        // signature/dict order: x, kc, vc, Wq, bq, Wk, bk, Wv, bv, Wo, bo
        x  = (const float*)d_in[0];
        kc = (const float*)d_in[1];
        vc = (const float*)d_in[2];
        Wq = (const float*)d_in[3];
        bq = (const float*)d_in[4];
        Wk = (const float*)d_in[5];
        bk = (const float*)d_in[6];
        Wv = (const float*)d_in[7];
        bv = (const float*)d_in[8];
        Wo = (const float*)d_in[9];
        bo = (const float*)d_in[10];
    } else {
        // alphabetical order: Wk, Wo, Wq, Wv, bk, bo, bq, bv, kc, vc, x
        Wk = (const float*)d_in[0];
        Wo = (const float*)d_in[1];
        Wq = (const float*)d_in[2];
        Wv = (const float*)d_in[3];
        bk = (const float*)d_in[4];
        bo = (const float*)d_in[5];
        bq = (const float*)d_in[6];
        bv = (const float*)d_in[7];
        kc = (const float*)d_in[8];
        vc = (const float*)d_in[9];
        x  = (const float*)d_in[10];
    }

    float* out  = (float*)d_out;                                   // [8,1,4096]
    float* kout = out + (size_t)BATCH * EDIM;                      // [8,32,2048,128]
    float* vout = kout + (size_t)BATCH * HEADS * TTOT * DHEAD;     // [8,32,2048,128]

    qkv_gemv<<<dim3(512, 3), 256>>>(x, Wq, bq, Wk, bk, Wv, bv);
    attn_kernel<<<dim3(NSPLIT, HEADS, BATCH), 256>>>(kc, vc, kout, vout);
    combine_kernel<<<BATCH * HEADS, DHEAD>>>();
    out_gemv<<<512, 256>>>(Wo, bo, out);
}

// round 8
// speedup vs baseline: 1.1520x; 1.1520x over previous
#include <cuda_runtime.h>

#define EDIM    4096
#define BATCH   8
#define HEADS   32
#define DHEAD   128
#define TPREV   2047
#define TTOT    2048
#define NSPLIT  8
#define TOK_PER_BLOCK 256   // 8 warps * 32 tokens

// ---------------- scratch (device globals, no allocation) ----------------
__device__ float g_q[BATCH * EDIM];
__device__ float g_k[BATCH * EDIM];
__device__ float g_v[BATCH * EDIM];
__device__ float g_attn[BATCH * EDIM];
__device__ float g_pm[BATCH * HEADS * NSPLIT];
__device__ float g_pl[BATCH * HEADS * NSPLIT];
__device__ float g_pacc[BATCH * HEADS * NSPLIT * DHEAD];

// ---------------- row-blocked GEMV, 16 rows/block ---------------------------
// Y[b][row] = sum_i X[b][i]*W[row][i] + bias[row]
// Block: 256 threads = 8 warps; each warp owns 2 DISTINCT W rows.
// x staged through 32KB smem chunks (one DRAM read per block).
// 2 K-steps unrolled -> 4 W float4 loads batched per macro-step (MLP>=4/warp),
// ~70 regs -> ~4 blocks/SM co-resident -> DRAM-bound.
__device__ __forceinline__ void gemv_body(const float* __restrict__ X,
                                          const float* __restrict__ W,
                                          const float* __restrict__ bias,
                                          float* __restrict__ Y,
                                          float* xs /* [8*1024] */) {
    const int warp = threadIdx.x >> 5;
    const int lane = threadIdx.x & 31;
    const int row0 = blockIdx.x * 16 + warp * 2;

    const float* w0p = W + (size_t)(row0 + 0) * EDIM;
    const float* w1p = W + (size_t)(row0 + 1) * EDIM;

    float acc[2][8];
#pragma unroll
    for (int r = 0; r < 2; ++r)
#pragma unroll
        for (int b = 0; b < 8; ++b) acc[r][b] = 0.f;

    for (int c = 0; c < 4; ++c) {
        const int base = c * 1024;
        __syncthreads();
        // stage x chunk: 8 batches x 1024 floats = 2048 float4
#pragma unroll
        for (int t = threadIdx.x; t < 2048; t += 256) {
            const int f = t * 4;
            const int b = f >> 10;
            const int i = f & 1023;
            *(float4*)&xs[b * 1024 + i] = *(const float4*)&X[b * EDIM + base + i];
        }
        __syncthreads();
        // 4 macro-steps x 2 sub-steps of 128 floats each
#pragma unroll
        for (int ms = 0; ms < 4; ++ms) {
            const int ia = ms * 256 + lane * 4;
            const int ib = ia + 128;
            // batch all 4 W loads up front (MLP)
            const float4 wa0 = *(const float4*)&w0p[base + ia];
            const float4 wa1 = *(const float4*)&w1p[base + ia];
            const float4 wb0 = *(const float4*)&w0p[base + ib];
            const float4 wb1 = *(const float4*)&w1p[base + ib];
#pragma unroll
            for (int b = 0; b < 8; ++b) {
                const float4 x4 = *(const float4*)&xs[b * 1024 + ia];
                acc[0][b] += wa0.x * x4.x + wa0.y * x4.y + wa0.z * x4.z + wa0.w * x4.w;
                acc[1][b] += wa1.x * x4.x + wa1.y * x4.y + wa1.z * x4.z + wa1.w * x4.w;
            }
#pragma unroll
            for (int b = 0; b < 8; ++b) {
                const float4 x4 = *(const float4*)&xs[b * 1024 + ib];
                acc[0][b] += wb0.x * x4.x + wb0.y * x4.y + wb0.z * x4.z + wb0.w * x4.w;
                acc[1][b] += wb1.x * x4.x + wb1.y * x4.y + wb1.z * x4.z + wb1.w * x4.w;
            }
        }
    }

    // warp-reduce 16 accumulators; lane = r*8+b (r<2) writes its result
#pragma unroll
    for (int r = 0; r < 2; ++r)
#pragma unroll
        for (int b = 0; b < 8; ++b) {
            float v = acc[r][b];
#pragma unroll
            for (int s = 16; s > 0; s >>= 1)
                v += __shfl_xor_sync(0xffffffffu, v, s);
            acc[r][b] = v;
        }
    if (lane < 16) {
        const int r = lane >> 3;
        const int b = lane & 7;
        Y[b * EDIM + row0 + r] = acc[r][b] + bias[row0 + r];
    }
}

// QKV fused over blockIdx.y; destinations are device globals referenced
// from DEVICE code only.
__global__ void qkv_gemv(const float* __restrict__ x,
                         const float* __restrict__ Wq, const float* __restrict__ bq,
                         const float* __restrict__ Wk, const float* __restrict__ bk,
                         const float* __restrict__ Wv, const float* __restrict__ bv) {
    __shared__ float xs[8 * 1024];
    const int p = blockIdx.y;
    const float* W    = (p == 0) ? Wq : (p == 1) ? Wk : Wv;
    const float* bias = (p == 0) ? bq : (p == 1) ? bk : bv;
    float* Y          = (p == 0) ? g_q : (p == 1) ? g_k : g_v;
    gemv_body(x, W, bias, Y, xs);
}

// Output projection: reads g_attn inside device code.
__global__ void out_gemv(const float* __restrict__ Wo,
                         const float* __restrict__ bo,
                         float* __restrict__ out) {
    __shared__ float xs[8 * 1024];
    gemv_body(g_attn, Wo, bo, out, xs);
}

// ---------------- fused cache-copy + flash attention ----------------------
// grid: (NSPLIT, HEADS, BATCH), block 256 (8 warps x 32 tokens each)
// NOTE: the reference slices q AFTER transposing to (b, h, s, d), so
// q[:, -1:] selects the LAST HEAD (h=31), broadcast to all heads.
__global__ void attn_kernel(const float* __restrict__ kc,
                            const float* __restrict__ vc,
                            float* __restrict__ kout,
                            float* __restrict__ vout) {
    const int split = blockIdx.x;
    const int h = blockIdx.y;
    const int b = blockIdx.z;
    const int warp = threadIdx.x >> 5;
    const int lane = threadIdx.x & 31;
    const int bh = b * HEADS + h;

    // q from head 31 for ALL heads (reference broadcast semantics)
    const float4 q4 = *(const float4*)&g_q[b * EDIM + (HEADS - 1) * DHEAD + lane * 4];
    const float scale = 0.08838834764831845f;  // 1/sqrt(128)

    float m = -1e30f, l = 0.f;
    float4 acc = make_float4(0.f, 0.f, 0.f, 0.f);

    const int tok0 = split * TOK_PER_BLOCK + warp * 32;

#pragma unroll 4
    for (int j = 0; j < 32; ++j) {
        const int tok = tok0 + j;
        const float* kp;
        const float* vp;
        if (tok < TPREV) {
            const size_t off = ((size_t)bh * TPREV + tok) * DHEAD;
            kp = kc + off;
            vp = vc + off;
        } else {
            kp = g_k + b * EDIM + h * DHEAD;
            vp = g_v + b * EDIM + h * DHEAD;
        }
        const float4 k4 = *(const float4*)&kp[lane * 4];
        const float4 v4 = *(const float4*)&vp[lane * 4];

        // cache copy rides the same read
        const size_t oo = ((size_t)bh * TTOT + tok) * DHEAD + lane * 4;
        *(float4*)&kout[oo] = k4;
        *(float4*)&vout[oo] = v4;

        float s = q4.x * k4.x + q4.y * k4.y + q4.z * k4.z + q4.w * k4.w;
#pragma unroll
        for (int sh = 16; sh > 0; sh >>= 1)
            s += __shfl_xor_sync(0xffffffffu, s, sh);
        s *= scale;

        const float mn = fmaxf(m, s);
        const float sc = __expf(m - mn);
        const float p  = __expf(s - mn);
        l = l * sc + p;
        acc.x = acc.x * sc + p * v4.x;
        acc.y = acc.y * sc + p * v4.y;
        acc.z = acc.z * sc + p * v4.z;
        acc.w = acc.w * sc + p * v4.w;
        m = mn;
    }

    // combine the 8 warps of this block
    __shared__ float sm_m[8], sm_l[8];
    __shared__ __align__(16) float sm_acc[8][DHEAD];
    if (lane == 0) { sm_m[warp] = m; sm_l[warp] = l; }
    *(float4*)&sm_acc[warp][lane * 4] = acc;
    __syncthreads();

    if (threadIdx.x < DHEAD) {
        const int d = threadIdx.x;
        float M = -1e30f;
#pragma unroll
        for (int w = 0; w < 8; ++w) M = fmaxf(M, sm_m[w]);
        float L = 0.f, A = 0.f;
#pragma unroll
        for (int w = 0; w < 8; ++w) {
            const float e = __expf(sm_m[w] - M);
            L += sm_l[w] * e;
            A += sm_acc[w][d] * e;
        }
        const int idx = bh * NSPLIT + split;
        g_pacc[idx * DHEAD + d] = A;
        if (d == 0) { g_pm[idx] = M; g_pl[idx] = L; }
    }
}

// merge NSPLIT partial softmaxes per (b,h)
__global__ void combine_kernel() {
    const int bh = blockIdx.x;   // 0..255
    const int d = threadIdx.x;   // 0..127
    float M = -1e30f;
#pragma unroll
    for (int s = 0; s < NSPLIT; ++s)
        M = fmaxf(M, g_pm[bh * NSPLIT + s]);
    float L = 0.f, A = 0.f;
#pragma unroll
    for (int s = 0; s < NSPLIT; ++s) {
        const float e = __expf(g_pm[bh * NSPLIT + s] - M);
        L += g_pl[bh * NSPLIT + s] * e;
        A += g_pacc[(bh * NSPLIT + s) * DHEAD + d] * e;
    }
    const int b = bh / HEADS;
    const int h = bh % HEADS;
    g_attn[b * EDIM + h * DHEAD + d] = A / L;
}

// ---------------- launch ---------------------------------------------------
extern "C" void kernel_launch(void* const* d_in, const int* in_sizes, int n_in,
                              void* d_out, int out_size) {
    // Defensive input mapping based on element counts.
    const float *x, *kc, *vc, *Wq, *bq, *Wk, *bk, *Wv, *bv, *Wo, *bo;
    if (in_sizes[0] == BATCH * EDIM) {
        // signature/dict order: x, kc, vc, Wq, bq, Wk, bk, Wv, bv, Wo, bo
        x  = (const float*)d_in[0];
        kc = (const float*)d_in[1];
        vc = (const float*)d_in[2];
        Wq = (const float*)d_in[3];
        bq = (const float*)d_in[4];
        Wk = (const float*)d_in[5];
        bk = (const float*)d_in[6];
        Wv = (const float*)d_in[7];
        bv = (const float*)d_in[8];
        Wo = (const float*)d_in[9];
        bo = (const float*)d_in[10];
    } else {
        // alphabetical order: Wk, Wo, Wq, Wv, bk, bo, bq, bv, kc, vc, x
        Wk = (const float*)d_in[0];
        Wo = (const float*)d_in[1];
        Wq = (const float*)d_in[2];
        Wv = (const float*)d_in[3];
        bk = (const float*)d_in[4];
        bo = (const float*)d_in[5];
        bq = (const float*)d_in[6];
        bv = (const float*)d_in[7];
        kc = (const float*)d_in[8];
        vc = (const float*)d_in[9];
        x  = (const float*)d_in[10];
    }

    float* out  = (float*)d_out;                                   // [8,1,4096]
    float* kout = out + (size_t)BATCH * EDIM;                      // [8,32,2048,128]
    float* vout = kout + (size_t)BATCH * HEADS * TTOT * DHEAD;     // [8,32,2048,128]

    qkv_gemv<<<dim3(256, 3), 256>>>(x, Wq, bq, Wk, bk, Wv, bv);
    attn_kernel<<<dim3(NSPLIT, HEADS, BATCH), 256>>>(kc, vc, kout, vout);
    combine_kernel<<<BATCH * HEADS, DHEAD>>>();
    out_gemv<<<256, 256>>>(Wo, bo, out);
}

// round 9
// speedup vs baseline: 1.2082x; 1.0487x over previous
#include <cuda_runtime.h>

#define EDIM    4096
#define BATCH   8
#define HEADS   32
#define DHEAD   128
#define TPREV   2047
#define TTOT    2048
#define NSPLIT  8
#define TOK_PER_BLOCK 256   // 8 warps * 32 tokens

#define GEMV_SMEM (BATCH * EDIM * sizeof(float))   // 128 KB dynamic smem

// ---------------- scratch (device globals, no allocation) ----------------
__device__ float g_q[BATCH * EDIM];
__device__ float g_k[BATCH * EDIM];
__device__ float g_v[BATCH * EDIM];
__device__ float g_attn[BATCH * EDIM];
__device__ float g_pm[BATCH * HEADS * NSPLIT];
__device__ float g_pl[BATCH * HEADS * NSPLIT];
__device__ float g_pacc[BATCH * HEADS * NSPLIT * DHEAD];

// ---------------- row-blocked GEMV, 32 rows/block, MLP-8 ------------------
// Y[b][row] = sum_i X[b][i]*W[row][i] + bias[row]
// Block: 256 threads = 8 warps; warp owns 4 DISTINCT W rows (smem:W = 2x).
// ENTIRE x (8x4096 = 128KB) staged in dynamic smem once -> sync-free
// mainloop. 8 W float4 loads batched per macro-step (4 rows x 2 K-steps)
// -> MLP 8/warp -> ~32KB in flight/SM -> DRAM-bound.
__device__ __forceinline__ void gemv_body(const float* __restrict__ X,
                                          const float* __restrict__ W,
                                          const float* __restrict__ bias,
                                          float* __restrict__ Y) {
    extern __shared__ float xs[];   // [BATCH * EDIM]
    const int warp = threadIdx.x >> 5;
    const int lane = threadIdx.x & 31;
    const int row0 = blockIdx.x * 32 + warp * 4;

    // stage all of x: 8192 float4 over 256 threads
#pragma unroll
    for (int t = threadIdx.x; t < 8192; t += 256) {
        const int b = t >> 10;
        const int i = (t & 1023) * 4;
        *(float4*)&xs[b * EDIM + i] = *(const float4*)&X[b * EDIM + i];
    }
    __syncthreads();

    float acc[4][8];
#pragma unroll
    for (int r = 0; r < 4; ++r)
#pragma unroll
        for (int b = 0; b < 8; ++b) acc[r][b] = 0.f;

    const float* w0 = W + (size_t)row0 * EDIM;

    // 16 macro-steps x 256 floats (2 K-steps of 128 each)
#pragma unroll 2
    for (int ms = 0; ms < 16; ++ms) {
        const int ia = ms * 256 + lane * 4;
        const int ib = ia + 128;
        float4 wa[4], wb[4];
#pragma unroll
        for (int r = 0; r < 4; ++r)
            wa[r] = *(const float4*)&w0[(size_t)r * EDIM + ia];
#pragma unroll
        for (int r = 0; r < 4; ++r)
            wb[r] = *(const float4*)&w0[(size_t)r * EDIM + ib];
#pragma unroll
        for (int b = 0; b < 8; ++b) {
            const float4 x4 = *(const float4*)&xs[b * EDIM + ia];
#pragma unroll
            for (int r = 0; r < 4; ++r) {
                acc[r][b] += wa[r].x * x4.x + wa[r].y * x4.y
                           + wa[r].z * x4.z + wa[r].w * x4.w;
            }
        }
#pragma unroll
        for (int b = 0; b < 8; ++b) {
            const float4 x4 = *(const float4*)&xs[b * EDIM + ib];
#pragma unroll
            for (int r = 0; r < 4; ++r) {
                acc[r][b] += wb[r].x * x4.x + wb[r].y * x4.y
                           + wb[r].z * x4.z + wb[r].w * x4.w;
            }
        }
    }

    // warp-reduce 32 accumulators; lane = r*8+b picks its result
#pragma unroll
    for (int r = 0; r < 4; ++r)
#pragma unroll
        for (int b = 0; b < 8; ++b) {
            float v = acc[r][b];
#pragma unroll
            for (int s = 16; s > 0; s >>= 1)
                v += __shfl_xor_sync(0xffffffffu, v, s);
            acc[r][b] = v;
        }
    const int r = lane >> 3;
    const int b = lane & 7;
    Y[b * EDIM + row0 + r] = acc[r][b] + bias[row0 + r];
}

// QKV fused over blockIdx.y; destinations are device globals referenced
// from DEVICE code only.
__global__ void qkv_gemv(const float* __restrict__ x,
                         const float* __restrict__ Wq, const float* __restrict__ bq,
                         const float* __restrict__ Wk, const float* __restrict__ bk,
                         const float* __restrict__ Wv, const float* __restrict__ bv) {
    const int p = blockIdx.y;
    const float* W    = (p == 0) ? Wq : (p == 1) ? Wk : Wv;
    const float* bias = (p == 0) ? bq : (p == 1) ? bk : bv;
    float* Y          = (p == 0) ? g_q : (p == 1) ? g_k : g_v;
    gemv_body(x, W, bias, Y);
}

// Output projection: reads g_attn inside device code.
__global__ void out_gemv(const float* __restrict__ Wo,
                         const float* __restrict__ bo,
                         float* __restrict__ out) {
    gemv_body(g_attn, Wo, bo, out);
}

// ---------------- fused cache-copy + flash attention ----------------------
// grid: (NSPLIT, HEADS, BATCH), block 256 (8 warps x 32 tokens each)
// NOTE: the reference slices q AFTER transposing to (b, h, s, d), so
// q[:, -1:] selects the LAST HEAD (h=31), broadcast to all heads.
__global__ void attn_kernel(const float* __restrict__ kc,
                            const float* __restrict__ vc,
                            float* __restrict__ kout,
                            float* __restrict__ vout) {
    const int split = blockIdx.x;
    const int h = blockIdx.y;
    const int b = blockIdx.z;
    const int warp = threadIdx.x >> 5;
    const int lane = threadIdx.x & 31;
    const int bh = b * HEADS + h;

    // q from head 31 for ALL heads (reference broadcast semantics)
    const float4 q4 = *(const float4*)&g_q[b * EDIM + (HEADS - 1) * DHEAD + lane * 4];
    const float scale = 0.08838834764831845f;  // 1/sqrt(128)

    float m = -1e30f, l = 0.f;
    float4 acc = make_float4(0.f, 0.f, 0.f, 0.f);

    const int tok0 = split * TOK_PER_BLOCK + warp * 32;

#pragma unroll 4
    for (int j = 0; j < 32; ++j) {
        const int tok = tok0 + j;
        const float* kp;
        const float* vp;
        if (tok < TPREV) {
            const size_t off = ((size_t)bh * TPREV + tok) * DHEAD;
            kp = kc + off;
            vp = vc + off;
        } else {
            kp = g_k + b * EDIM + h * DHEAD;
            vp = g_v + b * EDIM + h * DHEAD;
        }
        const float4 k4 = *(const float4*)&kp[lane * 4];
        const float4 v4 = *(const float4*)&vp[lane * 4];

        // cache copy rides the same read
        const size_t oo = ((size_t)bh * TTOT + tok) * DHEAD + lane * 4;
        *(float4*)&kout[oo] = k4;
        *(float4*)&vout[oo] = v4;

        float s = q4.x * k4.x + q4.y * k4.y + q4.z * k4.z + q4.w * k4.w;
#pragma unroll
        for (int sh = 16; sh > 0; sh >>= 1)
            s += __shfl_xor_sync(0xffffffffu, s, sh);
        s *= scale;

        const float mn = fmaxf(m, s);
        const float sc = __expf(m - mn);
        const float p  = __expf(s - mn);
        l = l * sc + p;
        acc.x = acc.x * sc + p * v4.x;
        acc.y = acc.y * sc + p * v4.y;
        acc.z = acc.z * sc + p * v4.z;
        acc.w = acc.w * sc + p * v4.w;
        m = mn;
    }

    // combine the 8 warps of this block
    __shared__ float sm_m[8], sm_l[8];
    __shared__ __align__(16) float sm_acc[8][DHEAD];
    if (lane == 0) { sm_m[warp] = m; sm_l[warp] = l; }
    *(float4*)&sm_acc[warp][lane * 4] = acc;
    __syncthreads();

    if (threadIdx.x < DHEAD) {
        const int d = threadIdx.x;
        float M = -1e30f;
#pragma unroll
        for (int w = 0; w < 8; ++w) M = fmaxf(M, sm_m[w]);
        float L = 0.f, A = 0.f;
#pragma unroll
        for (int w = 0; w < 8; ++w) {
            const float e = __expf(sm_m[w] - M);
            L += sm_l[w] * e;
            A += sm_acc[w][d] * e;
        }
        const int idx = bh * NSPLIT + split;
        g_pacc[idx * DHEAD + d] = A;
        if (d == 0) { g_pm[idx] = M; g_pl[idx] = L; }
    }
}

// merge NSPLIT partial softmaxes per (b,h)
__global__ void combine_kernel() {
    const int bh = blockIdx.x;   // 0..255
    const int d = threadIdx.x;   // 0..127
    float M = -1e30f;
#pragma unroll
    for (int s = 0; s < NSPLIT; ++s)
        M = fmaxf(M, g_pm[bh * NSPLIT + s]);
    float L = 0.f, A = 0.f;
#pragma unroll
    for (int s = 0; s < NSPLIT; ++s) {
        const float e = __expf(g_pm[bh * NSPLIT + s] - M);
        L += g_pl[bh * NSPLIT + s] * e;
        A += g_pacc[(bh * NSPLIT + s) * DHEAD + d] * e;
    }
    const int b = bh / HEADS;
    const int h = bh % HEADS;
    g_attn[b * EDIM + h * DHEAD + d] = A / L;
}

// ---------------- launch ---------------------------------------------------
extern "C" void kernel_launch(void* const* d_in, const int* in_sizes, int n_in,
                              void* d_out, int out_size) {
    // Defensive input mapping based on element counts.
    const float *x, *kc, *vc, *Wq, *bq, *Wk, *bk, *Wv, *bv, *Wo, *bo;
    if (in_sizes[0] == BATCH * EDIM) {
        // signature/dict order: x, kc, vc, Wq, bq, Wk, bk, Wv, bv, Wo, bo
        x  = (const float*)d_in[0];
        kc = (const float*)d_in[1];
        vc = (const float*)d_in[2];
        Wq = (const float*)d_in[3];
        bq = (const float*)d_in[4];
        Wk = (const float*)d_in[5];
        bk = (const float*)d_in[6];
        Wv = (const float*)d_in[7];
        bv = (const float*)d_in[8];
        Wo = (const float*)d_in[9];
        bo = (const float*)d_in[10];
    } else {
        // alphabetical order: Wk, Wo, Wq, Wv, bk, bo, bq, bv, kc, vc, x
        Wk = (const float*)d_in[0];
        Wo = (const float*)d_in[1];
        Wq = (const float*)d_in[2];
        Wv = (const float*)d_in[3];
        bk = (const float*)d_in[4];
        bo = (const float*)d_in[5];
        bq = (const float*)d_in[6];
        bv = (const float*)d_in[7];
        kc = (const float*)d_in[8];
        vc = (const float*)d_in[9];
        x  = (const float*)d_in[10];
    }

    float* out  = (float*)d_out;                                   // [8,1,4096]
    float* kout = out + (size_t)BATCH * EDIM;                      // [8,32,2048,128]
    float* vout = kout + (size_t)BATCH * HEADS * TTOT * DHEAD;     // [8,32,2048,128]

    // allow 128KB dynamic smem (idempotent; not a stream op, capture-safe)
    static int smem_set = 0;
    if (!smem_set) {
        cudaFuncSetAttribute(qkv_gemv, cudaFuncAttributeMaxDynamicSharedMemorySize,
                             (int)GEMV_SMEM);
        cudaFuncSetAttribute(out_gemv, cudaFuncAttributeMaxDynamicSharedMemorySize,
                             (int)GEMV_SMEM);
        smem_set = 1;
    }

    qkv_gemv<<<dim3(128, 3), 256, GEMV_SMEM>>>(x, Wq, bq, Wk, bk, Wv, bv);
    attn_kernel<<<dim3(NSPLIT, HEADS, BATCH), 256>>>(kc, vc, kout, vout);
    combine_kernel<<<BATCH * HEADS, DHEAD>>>();
    out_gemv<<<128, 256, GEMV_SMEM>>>(Wo, bo, out);
}

// round 10
// speedup vs baseline: 1.3580x; 1.1240x over previous
#include <cuda_runtime.h>

#define EDIM    4096
#define BATCH   8
#define HEADS   32
#define DHEAD   128
#define TPREV   2047
#define TTOT    2048
#define NSPLIT  8
#define TOK_PER_BLOCK 256   // 8 warps * 32 tokens

#define GEMV_THREADS 512
#define GEMV_SMEM (BATCH * EDIM * sizeof(float))   // 128 KB dynamic smem

// ---------------- scratch (device globals, no allocation) ----------------
__device__ float g_q[BATCH * EDIM];
__device__ float g_k[BATCH * EDIM];
__device__ float g_v[BATCH * EDIM];
__device__ float g_attn[BATCH * EDIM];
__device__ float g_pm[BATCH * HEADS * NSPLIT];
__device__ float g_pl[BATCH * HEADS * NSPLIT];
__device__ float g_pacc[BATCH * HEADS * NSPLIT * DHEAD];

// ---------------- row-blocked GEMV, 32 rows/block, 16 warps, K-split ------
// Y[b][row] = sum_i X[b][i]*W[row][i] + bias[row]
// Block: 512 threads = 16 warps. Warps 0-7 own rows (w*4..+4) over
// K[0:2048]; warps 8-15 the SAME rows over K[2048:4096]. W is still read
// exactly once per block; 16 resident warps cover DRAM latency.
// Entire x (128KB) staged in dynamic smem once -> sync-free mainloop.
__device__ __forceinline__ void gemv_body(const float* __restrict__ X,
                                          const float* __restrict__ W,
                                          const float* __restrict__ bias,
                                          float* __restrict__ Y) {
    extern __shared__ float xs[];                  // [BATCH * EDIM]
    __shared__ float buf[2][32][8];                // cross-half partials

    const int warp  = threadIdx.x >> 5;
    const int lane  = threadIdx.x & 31;
    const int wrow4 = warp & 7;                    // row group 0..7
    const int half  = warp >> 3;                   // K half 0..1
    const int row0  = blockIdx.x * 32 + wrow4 * 4;
    const int kbase = half * 2048;

    // stage all of x: 8192 float4 over 512 threads
#pragma unroll
    for (int t = threadIdx.x; t < 8192; t += GEMV_THREADS) {
        const int b = t >> 10;
        const int i = (t & 1023) * 4;
        *(float4*)&xs[b * EDIM + i] = *(const float4*)&X[b * EDIM + i];
    }
    __syncthreads();

    float acc[4][8];
#pragma unroll
    for (int r = 0; r < 4; ++r)
#pragma unroll
        for (int b = 0; b < 8; ++b) acc[r][b] = 0.f;

    const float* w0 = W + (size_t)row0 * EDIM + kbase;

    // 16 steps x 128 floats over this warp's 2048-wide K range
#pragma unroll 2
    for (int ms = 0; ms < 16; ++ms) {
        const int i = ms * 128 + lane * 4;
        float4 w4[4];
#pragma unroll
        for (int r = 0; r < 4; ++r)
            w4[r] = *(const float4*)&w0[(size_t)r * EDIM + i];
#pragma unroll
        for (int b = 0; b < 8; ++b) {
            const float4 x4 = *(const float4*)&xs[b * EDIM + kbase + i];
#pragma unroll
            for (int r = 0; r < 4; ++r) {
                acc[r][b] += w4[r].x * x4.x + w4[r].y * x4.y
                           + w4[r].z * x4.z + w4[r].w * x4.w;
            }
        }
    }

    // warp-reduce 32 accumulators; lane = r*8+b holds its value
#pragma unroll
    for (int r = 0; r < 4; ++r)
#pragma unroll
        for (int b = 0; b < 8; ++b) {
            float v = acc[r][b];
#pragma unroll
            for (int s = 16; s > 0; s >>= 1)
                v += __shfl_xor_sync(0xffffffffu, v, s);
            acc[r][b] = v;
        }
    {
        const int r = lane >> 3;
        const int b = lane & 7;
        buf[half][wrow4 * 4 + r][b] = acc[r][b];
    }
    __syncthreads();

    // merge the two K halves: 256 threads cover 32 rows x 8 batches
    if (threadIdx.x < 256) {
        const int rl = threadIdx.x >> 3;
        const int b  = threadIdx.x & 7;
        const int row = blockIdx.x * 32 + rl;
        Y[b * EDIM + row] = buf[0][rl][b] + buf[1][rl][b] + bias[row];
    }
}

// QKV fused over blockIdx.y; destinations are device globals referenced
// from DEVICE code only.
__global__ __launch_bounds__(GEMV_THREADS)
void qkv_gemv(const float* __restrict__ x,
              const float* __restrict__ Wq, const float* __restrict__ bq,
              const float* __restrict__ Wk, const float* __restrict__ bk,
              const float* __restrict__ Wv, const float* __restrict__ bv) {
    const int p = blockIdx.y;
    const float* W    = (p == 0) ? Wq : (p == 1) ? Wk : Wv;
    const float* bias = (p == 0) ? bq : (p == 1) ? bk : bv;
    float* Y          = (p == 0) ? g_q : (p == 1) ? g_k : g_v;
    gemv_body(x, W, bias, Y);
}

// Output projection: reads g_attn inside device code.
__global__ __launch_bounds__(GEMV_THREADS)
void out_gemv(const float* __restrict__ Wo,
              const float* __restrict__ bo,
              float* __restrict__ out) {
    gemv_body(g_attn, Wo, bo, out);
}

// ---------------- fused cache-copy + flash attention ----------------------
// grid: (NSPLIT, HEADS, BATCH), block 256 (8 warps x 32 tokens each)
// NOTE: the reference slices q AFTER transposing to (b, h, s, d), so
// q[:, -1:] selects the LAST HEAD (h=31), broadcast to all heads.
__global__ void attn_kernel(const float* __restrict__ kc,
                            const float* __restrict__ vc,
                            float* __restrict__ kout,
                            float* __restrict__ vout) {
    const int split = blockIdx.x;
    const int h = blockIdx.y;
    const int b = blockIdx.z;
    const int warp = threadIdx.x >> 5;
    const int lane = threadIdx.x & 31;
    const int bh = b * HEADS + h;

    // q from head 31 for ALL heads (reference broadcast semantics)
    const float4 q4 = *(const float4*)&g_q[b * EDIM + (HEADS - 1) * DHEAD + lane * 4];
    const float scale = 0.08838834764831845f;  // 1/sqrt(128)

    float m = -1e30f, l = 0.f;
    float4 acc = make_float4(0.f, 0.f, 0.f, 0.f);

    const int tok0 = split * TOK_PER_BLOCK + warp * 32;

#pragma unroll 4
    for (int j = 0; j < 32; ++j) {
        const int tok = tok0 + j;
        const float* kp;
        const float* vp;
        if (tok < TPREV) {
            const size_t off = ((size_t)bh * TPREV + tok) * DHEAD;
            kp = kc + off;
            vp = vc + off;
        } else {
            kp = g_k + b * EDIM + h * DHEAD;
            vp = g_v + b * EDIM + h * DHEAD;
        }
        const float4 k4 = *(const float4*)&kp[lane * 4];
        const float4 v4 = *(const float4*)&vp[lane * 4];

        // cache copy rides the same read
        const size_t oo = ((size_t)bh * TTOT + tok) * DHEAD + lane * 4;
        *(float4*)&kout[oo] = k4;
        *(float4*)&vout[oo] = v4;

        float s = q4.x * k4.x + q4.y * k4.y + q4.z * k4.z + q4.w * k4.w;
#pragma unroll
        for (int sh = 16; sh > 0; sh >>= 1)
            s += __shfl_xor_sync(0xffffffffu, s, sh);
        s *= scale;

        const float mn = fmaxf(m, s);
        const float sc = __expf(m - mn);
        const float p  = __expf(s - mn);
        l = l * sc + p;
        acc.x = acc.x * sc + p * v4.x;
        acc.y = acc.y * sc + p * v4.y;
        acc.z = acc.z * sc + p * v4.z;
        acc.w = acc.w * sc + p * v4.w;
        m = mn;
    }

    // combine the 8 warps of this block
    __shared__ float sm_m[8], sm_l[8];
    __shared__ __align__(16) float sm_acc[8][DHEAD];
    if (lane == 0) { sm_m[warp] = m; sm_l[warp] = l; }
    *(float4*)&sm_acc[warp][lane * 4] = acc;
    __syncthreads();

    if (threadIdx.x < DHEAD) {
        const int d = threadIdx.x;
        float M = -1e30f;
#pragma unroll
        for (int w = 0; w < 8; ++w) M = fmaxf(M, sm_m[w]);
        float L = 0.f, A = 0.f;
#pragma unroll
        for (int w = 0; w < 8; ++w) {
            const float e = __expf(sm_m[w] - M);
            L += sm_l[w] * e;
            A += sm_acc[w][d] * e;
        }
        const int idx = bh * NSPLIT + split;
        g_pacc[idx * DHEAD + d] = A;
        if (d == 0) { g_pm[idx] = M; g_pl[idx] = L; }
    }
}

// merge NSPLIT partial softmaxes per (b,h)
__global__ void combine_kernel() {
    const int bh = blockIdx.x;   // 0..255
    const int d = threadIdx.x;   // 0..127
    float M = -1e30f;
#pragma unroll
    for (int s = 0; s < NSPLIT; ++s)
        M = fmaxf(M, g_pm[bh * NSPLIT + s]);
    float L = 0.f, A = 0.f;
#pragma unroll
    for (int s = 0; s < NSPLIT; ++s) {
        const float e = __expf(g_pm[bh * NSPLIT + s] - M);
        L += g_pl[bh * NSPLIT + s] * e;
        A += g_pacc[(bh * NSPLIT + s) * DHEAD + d] * e;
    }
    const int b = bh / HEADS;
    const int h = bh % HEADS;
    g_attn[b * EDIM + h * DHEAD + d] = A / L;
}

// ---------------- launch ---------------------------------------------------
extern "C" void kernel_launch(void* const* d_in, const int* in_sizes, int n_in,
                              void* d_out, int out_size) {
    // Defensive input mapping based on element counts.
    const float *x, *kc, *vc, *Wq, *bq, *Wk, *bk, *Wv, *bv, *Wo, *bo;
    if (in_sizes[0] == BATCH * EDIM) {
        // signature/dict order: x, kc, vc, Wq, bq, Wk, bk, Wv, bv, Wo, bo
        x  = (const float*)d_in[0];
        kc = (const float*)d_in[1];
        vc = (const float*)d_in[2];
        Wq = (const float*)d_in[3];
        bq = (const float*)d_in[4];
        Wk = (const float*)d_in[5];
        bk = (const float*)d_in[6];
        Wv = (const float*)d_in[7];
        bv = (const float*)d_in[8];
        Wo = (const float*)d_in[9];
        bo = (const float*)d_in[10];
    } else {
        // alphabetical order: Wk, Wo, Wq, Wv, bk, bo, bq, bv, kc, vc, x
        Wk = (const float*)d_in[0];
        Wo = (const float*)d_in[1];
        Wq = (const float*)d_in[2];
        Wv = (const float*)d_in[3];
        bk = (const float*)d_in[4];
        bo = (const float*)d_in[5];
        bq = (const float*)d_in[6];
        bv = (const float*)d_in[7];
        kc = (const float*)d_in[8];
        vc = (const float*)d_in[9];
        x  = (const float*)d_in[10];
    }

    float* out  = (float*)d_out;                                   // [8,1,4096]
    float* kout = out + (size_t)BATCH * EDIM;                      // [8,32,2048,128]
    float* vout = kout + (size_t)BATCH * HEADS * TTOT * DHEAD;     // [8,32,2048,128]

    // allow 128KB dynamic smem (idempotent; capture-safe)
    static int smem_set = 0;
    if (!smem_set) {
        cudaFuncSetAttribute(qkv_gemv, cudaFuncAttributeMaxDynamicSharedMemorySize,
                             (int)GEMV_SMEM);
        cudaFuncSetAttribute(out_gemv, cudaFuncAttributeMaxDynamicSharedMemorySize,
                             (int)GEMV_SMEM);
        smem_set = 1;
    }

    qkv_gemv<<<dim3(128, 3), GEMV_THREADS, GEMV_SMEM>>>(x, Wq, bq, Wk, bk, Wv, bv);
    attn_kernel<<<dim3(NSPLIT, HEADS, BATCH), 256>>>(kc, vc, kout, vout);
    combine_kernel<<<BATCH * HEADS, DHEAD>>>();
    out_gemv<<<128, GEMV_THREADS, GEMV_SMEM>>>(Wo, bo, out);
}

// round 11
// speedup vs baseline: 1.4797x; 1.0896x over previous
#include <cuda_runtime.h>

#define EDIM    4096
#define BATCH   8
#define HEADS   32
#define DHEAD   128
#define TPREV   2047
#define TTOT    2048
#define NSPLIT  8
#define TOK_PER_BLOCK 256   // 8 warps * 32 tokens

#define GEMV_THREADS 512
#define GEMV_SMEM (BATCH * EDIM * sizeof(float))   // 128 KB dynamic smem

// ---------------- scratch (device globals, no allocation) ----------------
__device__ float g_q[BATCH * EDIM];   // only rows 3968..4095 (head 31) valid
__device__ float g_k[BATCH * EDIM];
__device__ float g_v[BATCH * EDIM];
__device__ float g_attn[BATCH * EDIM];
__device__ float g_pm[BATCH * HEADS * NSPLIT];
__device__ float g_pl[BATCH * HEADS * NSPLIT];
__device__ float g_pacc[BATCH * HEADS * NSPLIT * DHEAD];

// ---------------- row-blocked GEMV, 32 rows/block, 16 warps, K-split,
// ---------------- software-pipelined W prefetch ---------------------------
// Y[b][row] = sum_i X[b][i]*W[row][i] + bias[row], rows row_base + blk*32.
// Warps 0-7: K[0:2048]; warps 8-15: same rows, K[2048:4096].
// Next macro-step's 4 W float4s are loaded BEFORE computing the current
// step, keeping 4 LDG in flight per warp during compute.
__device__ __forceinline__ void gemv_body(const float* __restrict__ X,
                                          const float* __restrict__ W,
                                          const float* __restrict__ bias,
                                          float* __restrict__ Y,
                                          int row_base) {
    extern __shared__ float xs[];                  // [BATCH * EDIM]
    __shared__ float buf[2][32][8];                // cross-half partials

    const int warp  = threadIdx.x >> 5;
    const int lane  = threadIdx.x & 31;
    const int wrow4 = warp & 7;                    // row group 0..7
    const int half  = warp >> 3;                   // K half 0..1
    const int row0  = row_base + blockIdx.x * 32 + wrow4 * 4;
    const int kbase = half * 2048;

    // stage all of x: 8192 float4 over 512 threads
#pragma unroll
    for (int t = threadIdx.x; t < 8192; t += GEMV_THREADS) {
        const int b = t >> 10;
        const int i = (t & 1023) * 4;
        *(float4*)&xs[b * EDIM + i] = *(const float4*)&X[b * EDIM + i];
    }
    __syncthreads();

    float acc[4][8];
#pragma unroll
    for (int r = 0; r < 4; ++r)
#pragma unroll
        for (int b = 0; b < 8; ++b) acc[r][b] = 0.f;

    const float* w0 = W + (size_t)row0 * EDIM + kbase + lane * 4;

    // prologue: load macro-step 0
    float4 wc[4];
#pragma unroll
    for (int r = 0; r < 4; ++r)
        wc[r] = *(const float4*)&w0[(size_t)r * EDIM];

    // 16 macro-steps x 128 floats; prefetch step ms+1 before computing ms
#pragma unroll
    for (int ms = 0; ms < 16; ++ms) {
        float4 wn[4];
        if (ms < 15) {
#pragma unroll
            for (int r = 0; r < 4; ++r)
                wn[r] = *(const float4*)&w0[(size_t)r * EDIM + (ms + 1) * 128];
        }
        const int i = kbase + ms * 128 + lane * 4;
#pragma unroll
        for (int b = 0; b < 8; ++b) {
            const float4 x4 = *(const float4*)&xs[b * EDIM + i];
#pragma unroll
            for (int r = 0; r < 4; ++r) {
                acc[r][b] += wc[r].x * x4.x + wc[r].y * x4.y
                           + wc[r].z * x4.z + wc[r].w * x4.w;
            }
        }
#pragma unroll
        for (int r = 0; r < 4; ++r) wc[r] = wn[r];
    }

    // warp-reduce 32 accumulators; lane = r*8+b holds its value
#pragma unroll
    for (int r = 0; r < 4; ++r)
#pragma unroll
        for (int b = 0; b < 8; ++b) {
            float v = acc[r][b];
#pragma unroll
            for (int s = 16; s > 0; s >>= 1)
                v += __shfl_xor_sync(0xffffffffu, v, s);
            acc[r][b] = v;
        }
    {
        const int r = lane >> 3;
        const int b = lane & 7;
        buf[half][wrow4 * 4 + r][b] = acc[r][b];
    }
    __syncthreads();

    // merge the two K halves: 256 threads cover 32 rows x 8 batches
    if (threadIdx.x < 256) {
        const int rl = threadIdx.x >> 3;
        const int b  = threadIdx.x & 7;
        const int row = row_base + blockIdx.x * 32 + rl;
        Y[b * EDIM + row] = buf[0][rl][b] + buf[1][rl][b] + bias[row];
    }
}

// K and V projections (full 4096 rows each), fused over blockIdx.y.
__global__ __launch_bounds__(GEMV_THREADS)
void kv_gemv(const float* __restrict__ x,
             const float* __restrict__ Wk, const float* __restrict__ bk,
             const float* __restrict__ Wv, const float* __restrict__ bv) {
    const int p = blockIdx.y;
    const float* W    = (p == 0) ? Wk : Wv;
    const float* bias = (p == 0) ? bk : bv;
    float* Y          = (p == 0) ? g_k : g_v;
    gemv_body(x, W, bias, Y, 0);
}

// Q projection: the reference only uses head 31 -> rows 3968..4095 only.
__global__ __launch_bounds__(GEMV_THREADS)
void q_gemv(const float* __restrict__ x,
            const float* __restrict__ Wq, const float* __restrict__ bq) {
    gemv_body(x, Wq, bq, g_q, (HEADS - 1) * DHEAD);
}

// Output projection: reads g_attn inside device code.
__global__ __launch_bounds__(GEMV_THREADS)
void out_gemv(const float* __restrict__ Wo,
              const float* __restrict__ bo,
              float* __restrict__ out) {
    gemv_body(g_attn, Wo, bo, out, 0);
}

// ---------------- fused cache-copy + flash attention ----------------------
// grid: (NSPLIT, HEADS, BATCH), block 256 (8 warps x 32 tokens each)
// NOTE: the reference slices q AFTER transposing to (b, h, s, d), so
// q[:, -1:] selects the LAST HEAD (h=31), broadcast to all heads.
__global__ void attn_kernel(const float* __restrict__ kc,
                            const float* __restrict__ vc,
                            float* __restrict__ kout,
                            float* __restrict__ vout) {
    const int split = blockIdx.x;
    const int h = blockIdx.y;
    const int b = blockIdx.z;
    const int warp = threadIdx.x >> 5;
    const int lane = threadIdx.x & 31;
    const int bh = b * HEADS + h;

    // q from head 31 for ALL heads (reference broadcast semantics)
    const float4 q4 = *(const float4*)&g_q[b * EDIM + (HEADS - 1) * DHEAD + lane * 4];
    const float scale = 0.08838834764831845f;  // 1/sqrt(128)

    float m = -1e30f, l = 0.f;
    float4 acc = make_float4(0.f, 0.f, 0.f, 0.f);

    const int tok0 = split * TOK_PER_BLOCK + warp * 32;

#pragma unroll 4
    for (int j = 0; j < 32; ++j) {
        const int tok = tok0 + j;
        const float* kp;
        const float* vp;
        if (tok < TPREV) {
            const size_t off = ((size_t)bh * TPREV + tok) * DHEAD;
            kp = kc + off;
            vp = vc + off;
        } else {
            kp = g_k + b * EDIM + h * DHEAD;
            vp = g_v + b * EDIM + h * DHEAD;
        }
        const float4 k4 = *(const float4*)&kp[lane * 4];
        const float4 v4 = *(const float4*)&vp[lane * 4];

        // cache copy rides the same read
        const size_t oo = ((size_t)bh * TTOT + tok) * DHEAD + lane * 4;
        *(float4*)&kout[oo] = k4;
        *(float4*)&vout[oo] = v4;

        float s = q4.x * k4.x + q4.y * k4.y + q4.z * k4.z + q4.w * k4.w;
#pragma unroll
        for (int sh = 16; sh > 0; sh >>= 1)
            s += __shfl_xor_sync(0xffffffffu, s, sh);
        s *= scale;

        const float mn = fmaxf(m, s);
        const float sc = __expf(m - mn);
        const float p  = __expf(s - mn);
        l = l * sc + p;
        acc.x = acc.x * sc + p * v4.x;
        acc.y = acc.y * sc + p * v4.y;
        acc.z = acc.z * sc + p * v4.z;
        acc.w = acc.w * sc + p * v4.w;
        m = mn;
    }

    // combine the 8 warps of this block
    __shared__ float sm_m[8], sm_l[8];
    __shared__ __align__(16) float sm_acc[8][DHEAD];
    if (lane == 0) { sm_m[warp] = m; sm_l[warp] = l; }
    *(float4*)&sm_acc[warp][lane * 4] = acc;
    __syncthreads();

    if (threadIdx.x < DHEAD) {
        const int d = threadIdx.x;
        float M = -1e30f;
#pragma unroll
        for (int w = 0; w < 8; ++w) M = fmaxf(M, sm_m[w]);
        float L = 0.f, A = 0.f;
#pragma unroll
        for (int w = 0; w < 8; ++w) {
            const float e = __expf(sm_m[w] - M);
            L += sm_l[w] * e;
            A += sm_acc[w][d] * e;
        }
        const int idx = bh * NSPLIT + split;
        g_pacc[idx * DHEAD + d] = A;
        if (d == 0) { g_pm[idx] = M; g_pl[idx] = L; }
    }
}

// merge NSPLIT partial softmaxes per (b,h)
__global__ void combine_kernel() {
    const int bh = blockIdx.x;   // 0..255
    const int d = threadIdx.x;   // 0..127
    float M = -1e30f;
#pragma unroll
    for (int s = 0; s < NSPLIT; ++s)
        M = fmaxf(M, g_pm[bh * NSPLIT + s]);
    float L = 0.f, A = 0.f;
#pragma unroll
    for (int s = 0; s < NSPLIT; ++s) {
        const float e = __expf(g_pm[bh * NSPLIT + s] - M);
        L += g_pl[bh * NSPLIT + s] * e;
        A += g_pacc[(bh * NSPLIT + s) * DHEAD + d] * e;
    }
    const int b = bh / HEADS;
    const int h = bh % HEADS;
    g_attn[b * EDIM + h * DHEAD + d] = A / L;
}

// ---------------- launch ---------------------------------------------------
extern "C" void kernel_launch(void* const* d_in, const int* in_sizes, int n_in,
                              void* d_out, int out_size) {
    // Defensive input mapping based on element counts.
    const float *x, *kc, *vc, *Wq, *bq, *Wk, *bk, *Wv, *bv, *Wo, *bo;
    if (in_sizes[0] == BATCH * EDIM) {
        // signature/dict order: x, kc, vc, Wq, bq, Wk, bk, Wv, bv, Wo, bo
        x  = (const float*)d_in[0];
        kc = (const float*)d_in[1];
        vc = (const float*)d_in[2];
        Wq = (const float*)d_in[3];
        bq = (const float*)d_in[4];
        Wk = (const float*)d_in[5];
        bk = (const float*)d_in[6];
        Wv = (const float*)d_in[7];
        bv = (const float*)d_in[8];
        Wo = (const float*)d_in[9];
        bo = (const float*)d_in[10];
    } else {
        // alphabetical order: Wk, Wo, Wq, Wv, bk, bo, bq, bv, kc, vc, x
        Wk = (const float*)d_in[0];
        Wo = (const float*)d_in[1];
        Wq = (const float*)d_in[2];
        Wv = (const float*)d_in[3];
        bk = (const float*)d_in[4];
        bo = (const float*)d_in[5];
        bq = (const float*)d_in[6];
        bv = (const float*)d_in[7];
        kc = (const float*)d_in[8];
        vc = (const float*)d_in[9];
        x  = (const float*)d_in[10];
    }

    float* out  = (float*)d_out;                                   // [8,1,4096]
    float* kout = out + (size_t)BATCH * EDIM;                      // [8,32,2048,128]
    float* vout = kout + (size_t)BATCH * HEADS * TTOT * DHEAD;     // [8,32,2048,128]

    // allow 128KB dynamic smem (idempotent; capture-safe)
    static int smem_set = 0;
    if (!smem_set) {
        cudaFuncSetAttribute(kv_gemv, cudaFuncAttributeMaxDynamicSharedMemorySize,
                             (int)GEMV_SMEM);
        cudaFuncSetAttribute(q_gemv, cudaFuncAttributeMaxDynamicSharedMemorySize,
                             (int)GEMV_SMEM);
        cudaFuncSetAttribute(out_gemv, cudaFuncAttributeMaxDynamicSharedMemorySize,
                             (int)GEMV_SMEM);
        smem_set = 1;
    }

    kv_gemv<<<dim3(128, 2), GEMV_THREADS, GEMV_SMEM>>>(x, Wk, bk, Wv, bv);
    q_gemv<<<4, GEMV_THREADS, GEMV_SMEM>>>(x, Wq, bq);
    attn_kernel<<<dim3(NSPLIT, HEADS, BATCH), 256>>>(kc, vc, kout, vout);
    combine_kernel<<<BATCH * HEADS, DHEAD>>>();
    out_gemv<<<128, GEMV_THREADS, GEMV_SMEM>>>(Wo, bo, out);
}